// round 11
// baseline (speedup 1.0000x reference)
#include <cuda_runtime.h>
#include <cuda_bf16.h>
#include <math.h>

// RNN-T greedy decode, persistent kernel, 1024 thr/block.
// LSTM/pred fp32; joint via bf16 mma.sync + in-phase exact fp32 re-check.
// R11: contention-free padded grid barrier (acq/rel), weight-prefetch hoisting.
#define B 8
#define T 200
#define H 1024
#define NV 16385
#define BLANK 16384
#define MAXSYM 4
#define NSTEP (T * MAXSYM) // 800
#define G 148
#define NTHR 1024
#define JTILE 112          // vocab cols per block (148*112 = 16576 >= NV)
#define DELTA 0.0625f

// ---------------- device scratch ----------------
__device__ __align__(16) float g_encT[T * B * H];
__device__ __align__(16) float g_E[T * B * H];
__device__ __align__(16) unsigned g_WoutM[(size_t)G * 64 * 896 + 8192];   // mma pack
__device__ __align__(16) float g_WoutV[(size_t)16416 * 1024];             // fp32 [v][k] re-check
__device__ __align__(16) float g_Wl[(size_t)128 * 1024 * 64 + 512];       // [tile][k][wx32|wh32]
__device__ __align__(16) float g_WpT[H * H];                               // [j][k]
__device__ float g_h[B * H];
__device__ float g_c[B * H];
__device__ float g_h2[2][B * H];
__device__ float g_c2[2][B * H];
__device__ unsigned g_qmma[4096];  // q bf16x2: [kp(512)][b(8)]
__device__ float g_qbj[B * H];     // q fp32 [b][j] (re-check)
__device__ int   g_lastbuf[2][B];
__device__ int   g_advbuf[2][B];
__device__ unsigned long long g_afin[B];

// ---- padded barrier state: each counter on its own 256B line ----
struct __align__(256) PadCtr { unsigned v; unsigned pad[63]; };
__device__ PadCtr g_leafp[8];
__device__ PadCtr g_rootp;
__device__ PadCtr g_genp;

// ---------------- helpers ----------------
__device__ __forceinline__ unsigned long long ffma2(unsigned long long a,
                                                    unsigned long long b,
                                                    unsigned long long c) {
    unsigned long long d;
    asm("fma.rn.f32x2 %0, %1, %2, %3;" : "=l"(d) : "l"(a), "l"(b), "l"(c));
    return d;
}
__device__ __forceinline__ unsigned long long dup2(float w) {
    unsigned long long r;
    unsigned u = __float_as_uint(w);
    asm("mov.b64 %0, {%1, %1};" : "=l"(r) : "r"(u));
    return r;
}
__device__ __forceinline__ unsigned long long pack_key(float f, int v) {
    unsigned u = __float_as_uint(f);
    u = (u & 0x80000000u) ? ~u : (u | 0x80000000u);
    return ((unsigned long long)u << 32) | (unsigned)(BLANK - v);
}
__device__ __forceinline__ float sigm(float x) { return 1.0f / (1.0f + expf(-x)); }

__device__ __forceinline__ void grid_sync(int bid) {
    __syncthreads();
    if (threadIdx.x == 0) {
        unsigned gen;
        asm volatile("ld.relaxed.gpu.global.u32 %0, [%1];"
                     : "=r"(gen) : "l"(&g_genp.v) : "memory");
        int leaf = bid & 7;
        unsigned cnt = (leaf < 4) ? 19u : 18u;   // 4*19 + 4*18 = 148
        unsigned t;
        asm volatile("atom.release.gpu.global.add.u32 %0, [%1], 1;"
                     : "=r"(t) : "l"(&g_leafp[leaf].v) : "memory");
        if ((t % cnt) == cnt - 1u) {
            unsigned rt;
            asm volatile("atom.acq_rel.gpu.global.add.u32 %0, [%1], 1;"
                         : "=r"(rt) : "l"(&g_rootp.v) : "memory");
            if ((rt & 7u) == 7u) {
                asm volatile("red.release.gpu.global.add.u32 [%0], 1;"
                             :: "l"(&g_genp.v) : "memory");
            }
        }
        unsigned cur;
        do {
            asm volatile("ld.acquire.gpu.global.u32 %0, [%1];"
                         : "=r"(cur) : "l"(&g_genp.v) : "memory");
        } while (cur == gen);
    }
    __syncthreads();
}

// ---------------- setup kernels ----------------
__global__ void k_setup1(const float* __restrict__ enc, const float* __restrict__ W_pred) {
    __shared__ float tile[32][33];
    int bidx = blockIdx.x;
    int tx = threadIdx.x, ty = threadIdx.y;   // 32 x 8
    if (bidx < 1792) {
        int b = bidx & 7, kb = ((bidx >> 3) & 31) * 32, tb = (bidx >> 8) * 32;
#pragma unroll
        for (int i = 0; i < 4; i++) {
            int k = kb + ty + i * 8, t = tb + tx;
            tile[ty + i * 8][tx] = (t < T) ? enc[(size_t)b * H * T + (size_t)k * T + t] : 0.0f;
        }
        __syncthreads();
#pragma unroll
        for (int i = 0; i < 4; i++) {
            int t = tb + ty + i * 8, k = kb + tx;
            if (t < T) g_encT[((size_t)t * B + b) * H + k] = tile[tx][ty + i * 8];
        }
        if (bidx == 0) {
            int tid = ty * 32 + tx;
            for (int i = tid; i < B * H; i += 256) { g_h[i] = 0.0f; g_c[i] = 0.0f; }
            if (tid < B) g_afin[tid] = 0ull;
        }
    } else {
        int j = bidx - 1792;
        int kb = (j & 31) * 32, jb = (j >> 5) * 32;
#pragma unroll
        for (int i = 0; i < 4; i++)
            tile[ty + i * 8][tx] = W_pred[(size_t)(kb + ty + i * 8) * H + jb + tx];
        __syncthreads();
#pragma unroll
        for (int i = 0; i < 4; i++)
            g_WpT[(size_t)(jb + ty + i * 8) * H + kb + tx] = tile[tx][ty + i * 8];
    }
}

__global__ void k_setup2(const float* __restrict__ W_out, const float* __restrict__ Wx,
                         const float* __restrict__ Wh) {
    __shared__ float tile[32][33];
    int bid = blockIdx.x;
    int tid = threadIdx.x;   // 448
    if (bid < G * 64) {
        int tileI = bid >> 6, kt = bid & 63;
        if (tid < 448) {
            int ct = tid >> 5, r = tid & 31;
            int cloc = r >> 2, pq = r & 3;
            int v = tileI * JTILE + ct * 8 + cloc;
            int k0 = kt * 16 + 2 * pq;
            unsigned e[4];
#pragma unroll
            for (int i = 0; i < 4; i++) {
                int kk = (i < 2) ? (k0 + i) : (k0 + 6 + i);   // k0, k0+1, k0+8, k0+9
                float f = (v < NV) ? W_out[(size_t)kk * NV + v] : 0.0f;
                e[i] = (unsigned)__bfloat16_as_ushort(__float2bfloat16(f));
            }
            size_t idx64 = (size_t)bid * 448 + ct * 32 + r;
            g_WoutM[idx64 * 2 + 0] = (e[1] << 16) | e[0];
            g_WoutM[idx64 * 2 + 1] = (e[3] << 16) | e[2];
        }
    } else if (bid < G * 64 + 128 * 1024) {
        int j = bid - G * 64;
        int tileI = j >> 10, k = j & 1023;
        if (tid < 64) {
            float val;
            if (tid < 32) val = Wx[(size_t)k * 4096 + (tid >> 3) * 1024 + tileI * 8 + (tid & 7)];
            else { int l2 = tid - 32; val = Wh[(size_t)k * 4096 + (l2 >> 3) * 1024 + tileI * 8 + (l2 & 7)]; }
            g_Wl[((size_t)tileI * 1024 + k) * 64 + tid] = val;
        }
    } else if (tid < 256) {
        int j = bid - (G * 64 + 128 * 1024);
        int tile_k = j / 513, tile_v = j - tile_k * 513;
        int kb = tile_k * 32, vb = tile_v * 32;
        int tx = tid & 31, ty = tid >> 5;   // 32 x 8
#pragma unroll
        for (int i = 0; i < 4; i++) {
            int k = kb + ty + i * 8, v = vb + tx;
            tile[ty + i * 8][tx] = (v < NV) ? W_out[(size_t)k * NV + v] : 0.0f;
        }
        __syncthreads();
#pragma unroll
        for (int i = 0; i < 4; i++) {
            int v = vb + ty + i * 8, k = kb + tx;
            g_WoutV[(size_t)v * 1024 + k] = tile[tx][ty + i * 8];
        }
    }
}

__global__ void k_egemm(const float* __restrict__ W_enc, const float* __restrict__ b_joint) {
    __shared__ float xs[B * H];
    int t = blockIdx.y;
    int j = blockIdx.x * 256 + threadIdx.x;
    for (int idx = threadIdx.x; idx < B * H; idx += 256)
        xs[idx] = g_encT[(size_t)t * B * H + idx];
    __syncthreads();
    float acc[B];
#pragma unroll
    for (int b = 0; b < B; b++) acc[b] = 0.0f;
    for (int k = 0; k < H; k += 4) {
        float w0 = __ldg(&W_enc[(size_t)(k + 0) * H + j]);
        float w1 = __ldg(&W_enc[(size_t)(k + 1) * H + j]);
        float w2 = __ldg(&W_enc[(size_t)(k + 2) * H + j]);
        float w3 = __ldg(&W_enc[(size_t)(k + 3) * H + j]);
#pragma unroll
        for (int b = 0; b < B; b++) {
            float4 q4 = *(const float4*)&xs[b * H + k];
            acc[b] = fmaf(q4.x, w0, acc[b]);
            acc[b] = fmaf(q4.y, w1, acc[b]);
            acc[b] = fmaf(q4.z, w2, acc[b]);
            acc[b] = fmaf(q4.w, w3, acc[b]);
        }
    }
    float bj = __ldg(&b_joint[j]);
#pragma unroll
    for (int b = 0; b < B; b++)
        g_E[((size_t)t * B + b) * H + j] = acc[b] + bj;
}

// ---------------- persistent decode kernel ----------------
#define SMEM_FLOATS 33984

__global__ void __launch_bounds__(NTHR, 1)
k_decode(const float* __restrict__ emb, const float* __restrict__ bias,
         const float* __restrict__ b_out,
         const int* __restrict__ lens, float* __restrict__ out) {
    extern __shared__ float sm[];
    __shared__ int s_adv[8];
    __shared__ int s_last[8];
    __shared__ float s_gmax[8];
    __shared__ int s_ncand;
    __shared__ int s_cand[896];
    int tid = threadIdx.x, bid = blockIdx.x;

    for (int s = 0; s < NSTEP; s++) {
        int p = s & 1;
        int is_start = (s == 0);

        // ---- decisions for step s-1 ----
        if (tid < 8) {
            int b = tid, advance = 0, lastv = BLANK;
            if (s > 0) {
                int d = s - 1, dp = d & 1;
                unsigned long long key = g_afin[b];
                int sym = BLANK - (int)(unsigned)(key & 0xffffffffu);
                int t = d >> 2, u = d & 3;
                int active = (u == 0) ? (t < lens[b]) : g_advbuf[dp ^ 1][b];
                advance = (active && sym != BLANK) ? 1 : 0;
                int prev_last = (d == 0) ? BLANK : g_lastbuf[dp ^ 1][b];
                lastv = advance ? sym : prev_last;
                g_advbuf[dp][b] = advance;
                g_lastbuf[dp][b] = lastv;
                if (bid == 0)
                    out[(size_t)b * NSTEP + t * MAXSYM + u] = (float)(active ? sym : BLANK);
            }
            s_adv[tid] = advance;
            s_last[tid] = lastv;
        }
        __syncthreads();

        // ---- LSTM (blocks 0..127) ----
        if (bid < 128) {
            // static weight ring: issue BEFORE staging so latency overlaps it
            int kp = tid >> 5, jg = tid & 31;
            const float2* wp2 = (const float2*)(g_Wl + ((size_t)bid * 1024) * 64) + jg;
            int k0 = kp * 32;
            float2 buf[4];
#pragma unroll
            for (int i = 0; i < 4; i++) buf[i] = wp2[(size_t)(k0 + i) * 32];

            const float* h2prev = g_h2[p ^ 1];
            float* xs = sm;
            float* hs = sm + 8192;
#pragma unroll
            for (int bb = 0; bb < 8; bb++) {
                int adv = s_adv[bb];
                const float* hsrc = adv ? (h2prev + bb * H) : (g_h + bb * H);
                const float* xsrc = emb + (size_t)s_last[bb] * H;
                int k = tid;
                float hv = 0.0f, xv = 0.0f;
                if (!is_start) { hv = hsrc[k]; xv = __ldg(&xsrc[k]); }
                hs[k * 8 + bb] = hv;
                xs[k * 8 + bb] = xv;
            }
            __syncthreads();
            if (tid < 64) {   // commit h
                int idx = bid * 64 + tid;
                int b = idx >> 10, k = idx & 1023;
                g_h[idx] = hs[k * 8 + b];
            }

            {
                const unsigned long long* xh =
                    (jg < 16) ? (const unsigned long long*)xs : (const unsigned long long*)hs;
                unsigned long long acc[2][4];
#pragma unroll
                for (int c = 0; c < 2; c++)
#pragma unroll
                    for (int bp = 0; bp < 4; bp++) acc[c][bp] = 0ull;
#pragma unroll
                for (int kk = 0; kk < 32; kk += 4) {
#pragma unroll
                    for (int i = 0; i < 4; i++) {
                        float2 w = buf[i];
                        buf[i] = wp2[(size_t)(k0 + kk + 4 + i) * 32];
                        int k = k0 + kk + i;
                        unsigned long long w0 = dup2(w.x), w1 = dup2(w.y);
#pragma unroll
                        for (int bp = 0; bp < 4; bp++) {
                            unsigned long long xp = xh[k * 4 + bp];
                            acc[0][bp] = ffma2(xp, w0, acc[0][bp]);
                            acc[1][bp] = ffma2(xp, w1, acc[1][bp]);
                        }
                    }
                }
                unsigned long long* redu = (unsigned long long*)(sm + 16384);
#pragma unroll
                for (int c = 0; c < 2; c++)
#pragma unroll
                    for (int bp = 0; bp < 4; bp++)
                        redu[(c * 4 + bp) * NTHR + tid] = acc[c][bp];
            }
            __syncthreads();
            if (tid < 256) {
                int gc = tid >> 3, b = tid & 7;
                int jgx = gc >> 1, cc = gc & 1;
                int bp = b >> 1, half = b & 1;
                const float* redf = sm + 16384;
                float z = 0.0f;
#pragma unroll 8
                for (int kpp = 0; kpp < 32; kpp++) {
                    z += redf[((cc * 4 + bp) * NTHR + kpp * 32 + jgx) * 2 + half];
                    z += redf[((cc * 4 + bp) * NTHR + kpp * 32 + 16 + jgx) * 2 + half];
                }
                int gate = gc >> 3, ch = gc & 7;
                z += __ldg(&bias[gate * 1024 + bid * 8 + ch]);
                float* zs = sm + 32768;
                zs[gc * 8 + b] = z;
            }
            __syncthreads();
            if (tid < 64) {
                int b = tid & 7, ch = tid >> 3;
                int jh = bid * 8 + ch;
                const float* zs = sm + 32768;
                float zi = zs[(0 * 8 + ch) * 8 + b];
                float zf = zs[(1 * 8 + ch) * 8 + b];
                float zg = zs[(2 * 8 + ch) * 8 + b];
                float zo = zs[(3 * 8 + ch) * 8 + b];
                float c_eff = 0.0f;
                if (!is_start) c_eff = s_adv[b] ? g_c2[p ^ 1][b * H + jh] : g_c[b * H + jh];
                g_c[b * H + jh] = c_eff;
                float cn = sigm(zf) * c_eff + sigm(zi) * tanhf(zg);
                float hn = sigm(zo) * tanhf(cn);
                g_c2[p][b * H + jh] = cn;
                g_h2[p][b * H + jh] = hn;
            }
        }
        grid_sync(bid);

        // ---- pred (blocks 0..127); block 128 resets g_afin ----
        if (bid < 128) {
            // static weight loads first (overlap with h2 staging)
            int w = tid >> 5, lane = tid & 31;
            int jloc = w & 7, q4 = w >> 3;
            int j = bid * 8 + jloc;
            const float4* wp = (const float4*)(g_WpT + (size_t)j * H + q4 * 256);
            float4 wA = wp[lane];
            float4 wB = wp[32 + lane];

            const float* h2c = g_h2[p];
#pragma unroll
            for (int bb = 0; bb < 8; bb++) {
                int k = tid;
                sm[k * 8 + bb] = h2c[bb * H + k];
            }
            __syncthreads();
            const unsigned long long* hu = (const unsigned long long*)sm;
            unsigned long long acc[4];
#pragma unroll
            for (int bp = 0; bp < 4; bp++) acc[bp] = 0ull;
#pragma unroll
            for (int cIt = 0; cIt < 2; cIt++) {
                int k = q4 * 256 + cIt * 128 + lane * 4;
                float4 w4 = (cIt == 0) ? wA : wB;
                unsigned long long w0 = dup2(w4.x), w1 = dup2(w4.y);
                unsigned long long w2 = dup2(w4.z), w3 = dup2(w4.w);
#pragma unroll
                for (int bp = 0; bp < 4; bp++) {
                    acc[bp] = ffma2(hu[(k + 0) * 4 + bp], w0, acc[bp]);
                    acc[bp] = ffma2(hu[(k + 1) * 4 + bp], w1, acc[bp]);
                    acc[bp] = ffma2(hu[(k + 2) * 4 + bp], w2, acc[bp]);
                    acc[bp] = ffma2(hu[(k + 3) * 4 + bp], w3, acc[bp]);
                }
            }
            float a[8];
#pragma unroll
            for (int bp = 0; bp < 4; bp++) {
                unsigned lo, hi;
                asm("mov.b64 {%0, %1}, %2;" : "=r"(lo), "=r"(hi) : "l"(acc[bp]));
                a[bp * 2] = __uint_as_float(lo);
                a[bp * 2 + 1] = __uint_as_float(hi);
            }
#pragma unroll
            for (int off = 16; off > 0; off >>= 1)
#pragma unroll
                for (int b = 0; b < 8; b++)
                    a[b] += __shfl_down_sync(0xffffffffu, a[b], off);
            float* prsh = sm + 8192;
            if (lane == 0) {
#pragma unroll
                for (int b = 0; b < 8; b++)
                    prsh[q4 * 64 + jloc * 8 + b] = a[b];
            }
            __syncthreads();
            if (tid < 64) {
                int jl = tid >> 3, b = tid & 7;
                int jj = bid * 8 + jl;
                int t = s >> 2;
                float v = prsh[jl * 8 + b] + prsh[64 + jl * 8 + b]
                        + prsh[128 + jl * 8 + b] + prsh[192 + jl * 8 + b]
                        + g_E[((size_t)t * B + b) * H + jj];
                float qv = tanhf(v);
                g_qbj[b * 1024 + jj] = qv;
                float qo = __shfl_xor_sync(0xffffffffu, qv, 8);
                if ((jl & 1) == 0) {
                    unsigned lo = (unsigned)__bfloat16_as_ushort(__float2bfloat16(qv));
                    unsigned hi = (unsigned)__bfloat16_as_ushort(__float2bfloat16(qo));
                    g_qmma[(bid * 4 + (jl >> 1)) * 8 + b] = (hi << 16) | lo;
                }
            }
        } else if (bid == 128) {
            if (tid < 8) g_afin[tid] = 0ull;
        }
        grid_sync(bid);

        // ---- joint: bf16 HMMA logits + block-local fp32 re-check -> exact g_afin ----
        {
            int w = tid >> 5, lane = tid & 31;
            // static weight ring: issue BEFORE q staging
            unsigned long long ring[4];
            const unsigned long long* wb = (const unsigned long long*)g_WoutM
                + (size_t)bid * 28672 + (w >> 1) * 32 + lane;
            int kt0 = (w & 1) * 32;
            if (w < 28) {
#pragma unroll
                for (int i = 0; i < 4; i++) ring[i] = wb[(size_t)(kt0 + i) * 448];
            }

            unsigned* qsm = (unsigned*)sm;
            for (int i = tid; i < 4096; i += NTHR) qsm[i] = g_qmma[i];
            __syncthreads();
            float* ppart = sm + 16384;                    // [2][8][112]
            if (w < 28) {
                int ct = w >> 1, kh = w & 1;
                int g = lane >> 2, tig = lane & 3;
                float d0 = 0.0f, d1 = 0.0f, d2 = 0.0f, d3 = 0.0f;
                unsigned zero = 0u;
#pragma unroll
                for (int kk = 0; kk < 32; kk += 4) {
#pragma unroll
                    for (int i = 0; i < 4; i++) {
                        unsigned long long bw = ring[i];
                        ring[i] = wb[(size_t)(kt0 + kk + 4 + i) * 448];
                        int kt = kt0 + kk + i;
                        unsigned a0 = qsm[(kt * 8 + tig) * 8 + g];
                        unsigned a2 = qsm[(kt * 8 + 4 + tig) * 8 + g];
                        unsigned b0 = (unsigned)bw, b1 = (unsigned)(bw >> 32);
                        asm volatile(
                            "mma.sync.aligned.m16n8k16.row.col.f32.bf16.bf16.f32 "
                            "{%0,%1,%2,%3}, {%4,%5,%6,%7}, {%8,%9}, {%0,%1,%2,%3};"
                            : "+f"(d0), "+f"(d1), "+f"(d2), "+f"(d3)
                            : "r"(a0), "r"(zero), "r"(a2), "r"(zero), "r"(b0), "r"(b1));
                    }
                }
                int col = ct * 8 + tig * 2;
                ppart[(kh * 8 + g) * JTILE + col + 0] = d0;
                ppart[(kh * 8 + g) * JTILE + col + 1] = d1;
            }
            __syncthreads();
            float* logf = sm + 33024;
            if (tid < JTILE * 8) {
                int o = tid;
                int v = bid * JTILE + (o % JTILE);
                float sv = ppart[o] + ppart[896 + o];
                logf[o] = (v < NV) ? sv + __ldg(&b_out[v]) : -1e30f;
            }
            __syncthreads();
            float* spart = sm + 33920;
            if (tid < 64) {
                int b = tid >> 3, part = tid & 7;
                float m = -1e30f;
#pragma unroll
                for (int cc = 0; cc < 14; cc++)
                    m = fmaxf(m, logf[b * JTILE + part * 14 + cc]);
                spart[tid] = m;
            }
            __syncthreads();
            if (tid < 8) {
                float m = -1e30f;
#pragma unroll
                for (int pp = 0; pp < 8; pp++) m = fmaxf(m, spart[tid * 8 + pp]);
                s_gmax[tid] = m;
            }
            if (tid == 0) s_ncand = 0;
            __syncthreads();
            if (tid < JTILE * 8) {
                int o = tid, b = o / JTILE;
                if (logf[o] >= s_gmax[b] - DELTA) {
                    int i = atomicAdd(&s_ncand, 1);
                    s_cand[i] = (b << 16) | (bid * JTILE + (o - b * JTILE));
                }
            }
            __syncthreads();
            int nc = s_ncand;
            int w2 = tid >> 5, ln = tid & 31;
            for (int ci = w2; ci < nc; ci += 32) {
                int pk = s_cand[ci];
                int b = pk >> 16, v = pk & 0xffff;
                if (v < NV) {
                    const float* wv = g_WoutV + (size_t)v * 1024;
                    const float* qv = g_qbj + b * 1024;
                    float part = 0.0f;
#pragma unroll 8
                    for (int kk = ln; kk < 1024; kk += 32)
                        part = fmaf(wv[kk], qv[kk], part);
#pragma unroll
                    for (int off = 16; off > 0; off >>= 1)
                        part += __shfl_down_sync(0xffffffffu, part, off);
                    if (ln == 0)
                        atomicMax(&g_afin[b], pack_key(part + __ldg(&b_out[v]), v));
                }
            }
        }
        grid_sync(bid);
    }

    // ---- epilogue: final decision + h,c output ----
    {
        int d = NSTEP - 1, dp = d & 1;
        if (tid < 8) {
            int b = tid;
            unsigned long long key = g_afin[b];
            int sym = BLANK - (int)(unsigned)(key & 0xffffffffu);
            int t = d >> 2, u = d & 3;
            int active = (u == 0) ? (t < lens[b]) : g_advbuf[dp ^ 1][b];
            int advance = (active && sym != BLANK) ? 1 : 0;
            if (bid == 0)
                out[(size_t)b * NSTEP + t * MAXSYM + u] = (float)(active ? sym : BLANK);
            s_adv[tid] = advance;
        }
        __syncthreads();
        for (int i = bid * NTHR + tid; i < B * H; i += G * NTHR) {
            int b = i >> 10;
            float hf = s_adv[b] ? g_h2[dp][i] : g_h[i];
            float cf = s_adv[b] ? g_c2[dp][i] : g_c[i];
            out[B * NSTEP + i] = hf;
            out[B * NSTEP + B * H + i] = cf;
        }
    }
}

extern "C" void kernel_launch(void* const* d_in, const int* in_sizes, int n_in,
                              void* d_out, int out_size) {
    (void)in_sizes; (void)n_in; (void)out_size;
    const float* enc     = (const float*)d_in[0];
    const int*   lens    = (const int*)d_in[1];
    const float* emb     = (const float*)d_in[2];
    const float* Wx      = (const float*)d_in[3];
    const float* Wh      = (const float*)d_in[4];
    const float* bias    = (const float*)d_in[5];
    const float* W_enc   = (const float*)d_in[6];
    const float* W_pred  = (const float*)d_in[7];
    const float* b_joint = (const float*)d_in[8];
    const float* W_out   = (const float*)d_in[9];
    const float* b_out   = (const float*)d_in[10];
    float* out = (float*)d_out;

    static int configured = 0;
    if (!configured) {
        cudaFuncSetAttribute(k_decode, cudaFuncAttributeMaxDynamicSharedMemorySize,
                             SMEM_FLOATS * 4);
        configured = 1;
    }

    k_setup1<<<2816, dim3(32, 8)>>>(enc, W_pred);
    k_setup2<<<G * 64 + 128 * 1024 + 513 * 32, 448>>>(W_out, Wx, Wh);
    k_egemm<<<dim3(4, T), 256>>>(W_enc, b_joint);
    k_decode<<<G, NTHR, SMEM_FLOATS * 4>>>(emb, bias, b_out, lens, out);
}

// round 14
// speedup vs baseline: 1.4733x; 1.4733x over previous
#include <cuda_runtime.h>
#include <cuda_bf16.h>
#include <math.h>

// RNN-T greedy decode, persistent kernel, 1024 thr/block.
// LSTM/pred fp32; joint via bf16 mma.sync (HMMA) + in-phase exact fp32 re-check.
// R14: revert to R10 base + all-batches-done early exit (tail steps are provably blank).
#define B 8
#define T 200
#define H 1024
#define NV 16385
#define BLANK 16384
#define MAXSYM 4
#define NSTEP (T * MAXSYM) // 800
#define G 148
#define NTHR 1024
#define JTILE 112          // vocab cols per block (148*112 = 16576 >= NV)
#define DELTA 0.0625f

// ---------------- device scratch ----------------
__device__ __align__(16) float g_encT[T * B * H];
__device__ __align__(16) float g_E[T * B * H];
// mma-packed W_out: per (tile, kt16): 14 coltiles x 32 u64; u64 = (b0,b1) frags
__device__ __align__(16) unsigned g_WoutM[(size_t)G * 64 * 896 + 8192];
__device__ __align__(16) float g_WoutV[(size_t)16416 * 1024];          // fp32 [v][k] re-check
__device__ __align__(16) float g_Wl[(size_t)128 * 1024 * 64 + 512];    // [tile][k][wx32|wh32]
__device__ __align__(16) float g_WpT[H * H];                            // [j][k]
__device__ float g_h[B * H];
__device__ float g_c[B * H];
__device__ float g_h2[2][B * H];
__device__ float g_c2[2][B * H];
__device__ unsigned g_qmma[4096];  // q bf16x2: [kp(512)][b(8)]
__device__ float g_qbj[B * H];     // q fp32 [b][j] (re-check)
__device__ int   g_lastbuf[2][B];
__device__ int   g_advbuf[2][B];
__device__ unsigned long long g_afin[B];
__device__ unsigned g_leaf[8];
__device__ unsigned g_root;
__device__ unsigned g_gen;

// ---------------- helpers ----------------
__device__ __forceinline__ unsigned long long ffma2(unsigned long long a,
                                                    unsigned long long b,
                                                    unsigned long long c) {
    unsigned long long d;
    asm("fma.rn.f32x2 %0, %1, %2, %3;" : "=l"(d) : "l"(a), "l"(b), "l"(c));
    return d;
}
__device__ __forceinline__ unsigned long long dup2(float w) {
    unsigned long long r;
    unsigned u = __float_as_uint(w);
    asm("mov.b64 %0, {%1, %1};" : "=l"(r) : "r"(u));
    return r;
}
__device__ __forceinline__ unsigned long long pack_key(float f, int v) {
    unsigned u = __float_as_uint(f);
    u = (u & 0x80000000u) ? ~u : (u | 0x80000000u);
    return ((unsigned long long)u << 32) | (unsigned)(BLANK - v);
}
__device__ __forceinline__ float sigm(float x) { return 1.0f / (1.0f + expf(-x)); }

__device__ __forceinline__ void grid_sync(int bid) {
    __syncthreads();
    if (threadIdx.x == 0) {
        __threadfence();
        unsigned gen = *(volatile unsigned*)&g_gen;
        int leaf = bid & 7;
        unsigned cnt = (leaf < 4) ? 19u : 18u;
        unsigned t = atomicAdd(&g_leaf[leaf], 1u);
        if ((t % cnt) == cnt - 1u) {
            unsigned rt = atomicAdd(&g_root, 1u);
            if ((rt & 7u) == 7u) {
                __threadfence();
                atomicExch(&g_gen, gen + 1u);
            }
        }
        while (*(volatile unsigned*)&g_gen == gen) {}
        __threadfence();
    }
    __syncthreads();
}

// ---------------- setup kernels ----------------
__global__ void k_setup1(const float* __restrict__ enc, const float* __restrict__ W_pred) {
    __shared__ float tile[32][33];
    int bidx = blockIdx.x;
    int tx = threadIdx.x, ty = threadIdx.y;   // 32 x 8
    if (bidx < 1792) {
        int b = bidx & 7, kb = ((bidx >> 3) & 31) * 32, tb = (bidx >> 8) * 32;
#pragma unroll
        for (int i = 0; i < 4; i++) {
            int k = kb + ty + i * 8, t = tb + tx;
            tile[ty + i * 8][tx] = (t < T) ? enc[(size_t)b * H * T + (size_t)k * T + t] : 0.0f;
        }
        __syncthreads();
#pragma unroll
        for (int i = 0; i < 4; i++) {
            int t = tb + ty + i * 8, k = kb + tx;
            if (t < T) g_encT[((size_t)t * B + b) * H + k] = tile[tx][ty + i * 8];
        }
        if (bidx == 0) {
            int tid = ty * 32 + tx;
            for (int i = tid; i < B * H; i += 256) { g_h[i] = 0.0f; g_c[i] = 0.0f; }
            if (tid < B) g_afin[tid] = 0ull;
        }
    } else {
        int j = bidx - 1792;
        int kb = (j & 31) * 32, jb = (j >> 5) * 32;
#pragma unroll
        for (int i = 0; i < 4; i++)
            tile[ty + i * 8][tx] = W_pred[(size_t)(kb + ty + i * 8) * H + jb + tx];
        __syncthreads();
#pragma unroll
        for (int i = 0; i < 4; i++)
            g_WpT[(size_t)(jb + ty + i * 8) * H + kb + tx] = tile[tx][ty + i * 8];
    }
}

// segments: [0,9472) mma W_out pack ; [9472, +131072) Wl ; rest: W_out -> [v][k]
__global__ void k_setup2(const float* __restrict__ W_out, const float* __restrict__ Wx,
                         const float* __restrict__ Wh) {
    __shared__ float tile[32][33];
    int bid = blockIdx.x;
    int tid = threadIdx.x;   // 448
    if (bid < G * 64) {
        int tileI = bid >> 6, kt = bid & 63;
        if (tid < 448) {
            int ct = tid >> 5, r = tid & 31;
            int cloc = r >> 2, pq = r & 3;
            int v = tileI * JTILE + ct * 8 + cloc;
            int k0 = kt * 16 + 2 * pq;
            unsigned e[4];
#pragma unroll
            for (int i = 0; i < 4; i++) {
                int kk = (i < 2) ? (k0 + i) : (k0 + 6 + i);   // k0, k0+1, k0+8, k0+9
                float f = (v < NV) ? W_out[(size_t)kk * NV + v] : 0.0f;
                e[i] = (unsigned)__bfloat16_as_ushort(__float2bfloat16(f));
            }
            size_t idx64 = (size_t)bid * 448 + ct * 32 + r;
            g_WoutM[idx64 * 2 + 0] = (e[1] << 16) | e[0];
            g_WoutM[idx64 * 2 + 1] = (e[3] << 16) | e[2];
        }
    } else if (bid < G * 64 + 128 * 1024) {
        int j = bid - G * 64;
        int tileI = j >> 10, k = j & 1023;
        if (tid < 64) {
            float val;
            if (tid < 32) val = Wx[(size_t)k * 4096 + (tid >> 3) * 1024 + tileI * 8 + (tid & 7)];
            else { int l2 = tid - 32; val = Wh[(size_t)k * 4096 + (l2 >> 3) * 1024 + tileI * 8 + (l2 & 7)]; }
            g_Wl[((size_t)tileI * 1024 + k) * 64 + tid] = val;
        }
    } else if (tid < 256) {
        int j = bid - (G * 64 + 128 * 1024);
        int tile_k = j / 513, tile_v = j - tile_k * 513;
        int kb = tile_k * 32, vb = tile_v * 32;
        int tx = tid & 31, ty = tid >> 5;   // 32 x 8
#pragma unroll
        for (int i = 0; i < 4; i++) {
            int k = kb + ty + i * 8, v = vb + tx;
            tile[ty + i * 8][tx] = (v < NV) ? W_out[(size_t)k * NV + v] : 0.0f;
        }
        __syncthreads();
#pragma unroll
        for (int i = 0; i < 4; i++) {
            int v = vb + ty + i * 8, k = kb + tx;
            g_WoutV[(size_t)v * 1024 + k] = tile[tx][ty + i * 8];
        }
    }
}

__global__ void k_egemm(const float* __restrict__ W_enc, const float* __restrict__ b_joint) {
    __shared__ float xs[B * H];
    int t = blockIdx.y;
    int j = blockIdx.x * 256 + threadIdx.x;
    for (int idx = threadIdx.x; idx < B * H; idx += 256)
        xs[idx] = g_encT[(size_t)t * B * H + idx];
    __syncthreads();
    float acc[B];
#pragma unroll
    for (int b = 0; b < B; b++) acc[b] = 0.0f;
    for (int k = 0; k < H; k += 4) {
        float w0 = __ldg(&W_enc[(size_t)(k + 0) * H + j]);
        float w1 = __ldg(&W_enc[(size_t)(k + 1) * H + j]);
        float w2 = __ldg(&W_enc[(size_t)(k + 2) * H + j]);
        float w3 = __ldg(&W_enc[(size_t)(k + 3) * H + j]);
#pragma unroll
        for (int b = 0; b < B; b++) {
            float4 q4 = *(const float4*)&xs[b * H + k];
            acc[b] = fmaf(q4.x, w0, acc[b]);
            acc[b] = fmaf(q4.y, w1, acc[b]);
            acc[b] = fmaf(q4.z, w2, acc[b]);
            acc[b] = fmaf(q4.w, w3, acc[b]);
        }
    }
    float bj = __ldg(&b_joint[j]);
#pragma unroll
    for (int b = 0; b < B; b++)
        g_E[((size_t)t * B + b) * H + j] = acc[b] + bj;
}

// ---------------- persistent decode kernel ----------------
#define SMEM_FLOATS 33984

__global__ void __launch_bounds__(NTHR, 1)
k_decode(const float* __restrict__ emb, const float* __restrict__ bias,
         const float* __restrict__ b_out,
         const int* __restrict__ lens, float* __restrict__ out) {
    extern __shared__ float sm[];
    __shared__ int s_adv[8];
    __shared__ int s_last[8];
    __shared__ float s_gmax[8];
    __shared__ int s_ncand;
    __shared__ int s_alldone;
    __shared__ int s_cand[896];
    int tid = threadIdx.x, bid = blockIdx.x;
    int exit_s = -1;

    for (int s = 0; s < NSTEP; s++) {
        int p = s & 1;
        int is_start = (s == 0);

        // ---- decisions for step s-1 (g_afin is exact fp32 argmax) ----
        if (tid < 8) {
            int b = tid, advance = 0, lastv = BLANK;
            if (s > 0) {
                int d = s - 1, dp = d & 1;
                unsigned long long key = g_afin[b];
                int sym = BLANK - (int)(unsigned)(key & 0xffffffffu);
                int t = d >> 2, u = d & 3;
                int active = (u == 0) ? (t < lens[b]) : g_advbuf[dp ^ 1][b];
                advance = (active && sym != BLANK) ? 1 : 0;
                int prev_last = (d == 0) ? BLANK : g_lastbuf[dp ^ 1][b];
                lastv = advance ? sym : prev_last;
                g_advbuf[dp][b] = advance;
                g_lastbuf[dp][b] = lastv;
                if (bid == 0)
                    out[(size_t)b * NSTEP + t * MAXSYM + u] = (float)(active ? sym : BLANK);
            }
            s_adv[tid] = advance;
            s_last[tid] = lastv;
        }
        // early-exit check: once t >= lens[b] for ALL b, every remaining output
        // is deterministically BLANK and state is frozen (identical to reference).
        if (tid == 32) {
            int t_cur = s >> 2, ad = 1;
#pragma unroll
            for (int b = 0; b < 8; b++) ad &= (t_cur >= lens[b]);
            s_alldone = ad;
        }
        __syncthreads();
        if (s_alldone) {
            if (bid == 0) {
                for (int i = tid; i < (NSTEP - s) * B; i += NTHR) {
                    int ss = s + i / B, b = i - (i / B) * B;
                    out[(size_t)b * NSTEP + ss] = (float)BLANK;
                }
            }
            exit_s = s;
            break;
        }

        // ---- LSTM (blocks 0..127) ----
        if (bid < 128) {
            const float* h2prev = g_h2[p ^ 1];
            float* xs = sm;
            float* hs = sm + 8192;
#pragma unroll
            for (int bb = 0; bb < 8; bb++) {
                int adv = s_adv[bb];
                const float* hsrc = adv ? (h2prev + bb * H) : (g_h + bb * H);
                const float* xsrc = emb + (size_t)s_last[bb] * H;
                int k = tid;
                float hv = 0.0f, xv = 0.0f;
                if (!is_start) { hv = hsrc[k]; xv = __ldg(&xsrc[k]); }
                hs[k * 8 + bb] = hv;
                xs[k * 8 + bb] = xv;
            }
            __syncthreads();
            if (tid < 64) {   // commit h
                int idx = bid * 64 + tid;
                int b = idx >> 10, k = idx & 1023;
                g_h[idx] = hs[k * 8 + b];
            }

            {
                int kp = tid >> 5;        // 32 k-chunks of 32
                int jg = tid & 31;        // gate-col pair (jg<16 wx, >=16 wh)
                const float2* wp2 = (const float2*)(g_Wl + ((size_t)bid * 1024) * 64) + jg;
                const unsigned long long* xh =
                    (jg < 16) ? (const unsigned long long*)xs : (const unsigned long long*)hs;
                unsigned long long acc[2][4];
#pragma unroll
                for (int c = 0; c < 2; c++)
#pragma unroll
                    for (int bp = 0; bp < 4; bp++) acc[c][bp] = 0ull;
                int k0 = kp * 32;
                float2 buf[4];
#pragma unroll
                for (int i = 0; i < 4; i++) buf[i] = wp2[(size_t)(k0 + i) * 32];
#pragma unroll
                for (int kk = 0; kk < 32; kk += 4) {
#pragma unroll
                    for (int i = 0; i < 4; i++) {
                        float2 w = buf[i];
                        buf[i] = wp2[(size_t)(k0 + kk + 4 + i) * 32];
                        int k = k0 + kk + i;
                        unsigned long long w0 = dup2(w.x), w1 = dup2(w.y);
#pragma unroll
                        for (int bp = 0; bp < 4; bp++) {
                            unsigned long long xp = xh[k * 4 + bp];
                            acc[0][bp] = ffma2(xp, w0, acc[0][bp]);
                            acc[1][bp] = ffma2(xp, w1, acc[1][bp]);
                        }
                    }
                }
                unsigned long long* redu = (unsigned long long*)(sm + 16384);
#pragma unroll
                for (int c = 0; c < 2; c++)
#pragma unroll
                    for (int bp = 0; bp < 4; bp++)
                        redu[(c * 4 + bp) * NTHR + tid] = acc[c][bp];
            }
            __syncthreads();
            if (tid < 256) {
                int gc = tid >> 3, b = tid & 7;
                int jgx = gc >> 1, cc = gc & 1;
                int bp = b >> 1, half = b & 1;
                const float* redf = sm + 16384;
                float z = 0.0f;
#pragma unroll 8
                for (int kp = 0; kp < 32; kp++) {
                    z += redf[((cc * 4 + bp) * NTHR + kp * 32 + jgx) * 2 + half];
                    z += redf[((cc * 4 + bp) * NTHR + kp * 32 + 16 + jgx) * 2 + half];
                }
                int gate = gc >> 3, ch = gc & 7;
                z += __ldg(&bias[gate * 1024 + bid * 8 + ch]);
                float* zs = sm + 32768;
                zs[gc * 8 + b] = z;
            }
            __syncthreads();
            if (tid < 64) {
                int b = tid & 7, ch = tid >> 3;
                int jh = bid * 8 + ch;
                const float* zs = sm + 32768;
                float zi = zs[(0 * 8 + ch) * 8 + b];
                float zf = zs[(1 * 8 + ch) * 8 + b];
                float zg = zs[(2 * 8 + ch) * 8 + b];
                float zo = zs[(3 * 8 + ch) * 8 + b];
                float c_eff = 0.0f;
                if (!is_start) c_eff = s_adv[b] ? g_c2[p ^ 1][b * H + jh] : g_c[b * H + jh];
                g_c[b * H + jh] = c_eff;
                float cn = sigm(zf) * c_eff + sigm(zi) * tanhf(zg);
                float hn = sigm(zo) * tanhf(cn);
                g_c2[p][b * H + jh] = cn;
                g_h2[p][b * H + jh] = hn;
            }
        }
        grid_sync(bid);

        // ---- pred (blocks 0..127); block 128 resets g_afin ----
        if (bid < 128) {
            const float* h2c = g_h2[p];
#pragma unroll
            for (int bb = 0; bb < 8; bb++) {
                int k = tid;
                sm[k * 8 + bb] = h2c[bb * H + k];
            }
            __syncthreads();
            int w = tid >> 5, lane = tid & 31;
            int jloc = w & 7, q4 = w >> 3;
            int j = bid * 8 + jloc;
            const float4* wp = (const float4*)(g_WpT + (size_t)j * H + q4 * 256);
            const unsigned long long* hu = (const unsigned long long*)sm;
            float4 wA = wp[lane];
            float4 wB = wp[32 + lane];
            unsigned long long acc[4];
#pragma unroll
            for (int bp = 0; bp < 4; bp++) acc[bp] = 0ull;
#pragma unroll
            for (int cIt = 0; cIt < 2; cIt++) {
                int k = q4 * 256 + cIt * 128 + lane * 4;
                float4 w4 = (cIt == 0) ? wA : wB;
                unsigned long long w0 = dup2(w4.x), w1 = dup2(w4.y);
                unsigned long long w2 = dup2(w4.z), w3 = dup2(w4.w);
#pragma unroll
                for (int bp = 0; bp < 4; bp++) {
                    acc[bp] = ffma2(hu[(k + 0) * 4 + bp], w0, acc[bp]);
                    acc[bp] = ffma2(hu[(k + 1) * 4 + bp], w1, acc[bp]);
                    acc[bp] = ffma2(hu[(k + 2) * 4 + bp], w2, acc[bp]);
                    acc[bp] = ffma2(hu[(k + 3) * 4 + bp], w3, acc[bp]);
                }
            }
            float a[8];
#pragma unroll
            for (int bp = 0; bp < 4; bp++) {
                unsigned lo, hi;
                asm("mov.b64 {%0, %1}, %2;" : "=r"(lo), "=r"(hi) : "l"(acc[bp]));
                a[bp * 2] = __uint_as_float(lo);
                a[bp * 2 + 1] = __uint_as_float(hi);
            }
#pragma unroll
            for (int off = 16; off > 0; off >>= 1)
#pragma unroll
                for (int b = 0; b < 8; b++)
                    a[b] += __shfl_down_sync(0xffffffffu, a[b], off);
            float* prsh = sm + 8192;
            if (lane == 0) {
#pragma unroll
                for (int b = 0; b < 8; b++)
                    prsh[q4 * 64 + jloc * 8 + b] = a[b];
            }
            __syncthreads();
            if (tid < 64) {
                int jl = tid >> 3, b = tid & 7;
                int jj = bid * 8 + jl;
                int t = s >> 2;
                float v = prsh[jl * 8 + b] + prsh[64 + jl * 8 + b]
                        + prsh[128 + jl * 8 + b] + prsh[192 + jl * 8 + b]
                        + g_E[((size_t)t * B + b) * H + jj];
                float qv = tanhf(v);
                g_qbj[b * 1024 + jj] = qv;
                float qo = __shfl_xor_sync(0xffffffffu, qv, 8);
                if ((jl & 1) == 0) {
                    unsigned lo = (unsigned)__bfloat16_as_ushort(__float2bfloat16(qv));
                    unsigned hi = (unsigned)__bfloat16_as_ushort(__float2bfloat16(qo));
                    g_qmma[(bid * 4 + (jl >> 1)) * 8 + b] = (hi << 16) | lo;
                }
            }
        } else if (bid == 128) {
            if (tid < 8) g_afin[tid] = 0ull;
        }
        grid_sync(bid);

        // ---- joint: bf16 HMMA logits + block-local fp32 re-check -> exact g_afin ----
        {
            unsigned* qsm = (unsigned*)sm;               // [0,4096) u32 = q bf16 pairs
            for (int i = tid; i < 4096; i += NTHR) qsm[i] = g_qmma[i];
            __syncthreads();
            float* ppart = sm + 16384;                    // [2][8][112]
            int w = tid >> 5, lane = tid & 31;
            if (w < 28) {
                int ct = w >> 1, kh = w & 1;
                int g = lane >> 2, tig = lane & 3;
                const unsigned long long* wb = (const unsigned long long*)g_WoutM
                    + (size_t)bid * 28672 + ct * 32 + lane;
                float d0 = 0.0f, d1 = 0.0f, d2 = 0.0f, d3 = 0.0f;
                unsigned zero = 0u;
                int kt0 = kh * 32;
                unsigned long long ring[4];
#pragma unroll
                for (int i = 0; i < 4; i++) ring[i] = wb[(size_t)(kt0 + i) * 448];
#pragma unroll
                for (int kk = 0; kk < 32; kk += 4) {
#pragma unroll
                    for (int i = 0; i < 4; i++) {
                        unsigned long long bw = ring[i];
                        ring[i] = wb[(size_t)(kt0 + kk + 4 + i) * 448];
                        int kt = kt0 + kk + i;
                        unsigned a0 = qsm[(kt * 8 + tig) * 8 + g];
                        unsigned a2 = qsm[(kt * 8 + 4 + tig) * 8 + g];
                        unsigned b0 = (unsigned)bw, b1 = (unsigned)(bw >> 32);
                        asm volatile(
                            "mma.sync.aligned.m16n8k16.row.col.f32.bf16.bf16.f32 "
                            "{%0,%1,%2,%3}, {%4,%5,%6,%7}, {%8,%9}, {%0,%1,%2,%3};"
                            : "+f"(d0), "+f"(d1), "+f"(d2), "+f"(d3)
                            : "r"(a0), "r"(zero), "r"(a2), "r"(zero), "r"(b0), "r"(b1));
                    }
                }
                int col = ct * 8 + tig * 2;
                ppart[(kh * 8 + g) * JTILE + col + 0] = d0;
                ppart[(kh * 8 + g) * JTILE + col + 1] = d1;
            }
            __syncthreads();
            float* logf = sm + 33024;
            if (tid < JTILE * 8) {
                int o = tid;
                int v = bid * JTILE + (o % JTILE);
                float sv = ppart[o] + ppart[896 + o];
                logf[o] = (v < NV) ? sv + __ldg(&b_out[v]) : -1e30f;
            }
            __syncthreads();
            float* spart = sm + 33920;
            if (tid < 64) {
                int b = tid >> 3, part = tid & 7;
                float m = -1e30f;
#pragma unroll
                for (int cc = 0; cc < 14; cc++)
                    m = fmaxf(m, logf[b * JTILE + part * 14 + cc]);
                spart[tid] = m;
            }
            __syncthreads();
            if (tid < 8) {
                float m = -1e30f;
#pragma unroll
                for (int pp = 0; pp < 8; pp++) m = fmaxf(m, spart[tid * 8 + pp]);
                s_gmax[tid] = m;
            }
            if (tid == 0) s_ncand = 0;
            __syncthreads();
            if (tid < JTILE * 8) {
                int o = tid, b = o / JTILE;
                if (logf[o] >= s_gmax[b] - DELTA) {
                    int i = atomicAdd(&s_ncand, 1);
                    s_cand[i] = (b << 16) | (bid * JTILE + (o - b * JTILE));
                }
            }
            __syncthreads();
            int nc = s_ncand;
            int w2 = tid >> 5, ln = tid & 31;
            for (int ci = w2; ci < nc; ci += 32) {
                int pk = s_cand[ci];
                int b = pk >> 16, v = pk & 0xffff;
                if (v < NV) {
                    const float* wv = g_WoutV + (size_t)v * 1024;
                    const float* qv = g_qbj + b * 1024;
                    float part = 0.0f;
#pragma unroll 8
                    for (int kk = ln; kk < 1024; kk += 32)
                        part = fmaf(wv[kk], qv[kk], part);
#pragma unroll
                    for (int off = 16; off > 0; off >>= 1)
                        part += __shfl_down_sync(0xffffffffu, part, off);
                    if (ln == 0)
                        atomicMax(&g_afin[b], pack_key(part + __ldg(&b_out[v]), v));
                }
            }
        }
        grid_sync(bid);
    }

    // ---- epilogue ----
    if (exit_s >= 0) {
        // early exit: labels already written (decisions + blank fill).
        // Final h,c = state after step exit_s-1's decision (s_adv still in shared).
        int dp = (exit_s - 1) & 1;
        for (int i = bid * NTHR + tid; i < B * H; i += G * NTHR) {
            int b = i >> 10;
            float hf = s_adv[b] ? g_h2[dp][i] : g_h[i];
            float cf = s_adv[b] ? g_c2[dp][i] : g_c[i];
            out[B * NSTEP + i] = hf;
            out[B * NSTEP + B * H + i] = cf;
        }
    } else {
        int d = NSTEP - 1, dp = d & 1;
        if (tid < 8) {
            int b = tid;
            unsigned long long key = g_afin[b];
            int sym = BLANK - (int)(unsigned)(key & 0xffffffffu);
            int t = d >> 2, u = d & 3;
            int active = (u == 0) ? (t < lens[b]) : g_advbuf[dp ^ 1][b];
            int advance = (active && sym != BLANK) ? 1 : 0;
            if (bid == 0)
                out[(size_t)b * NSTEP + t * MAXSYM + u] = (float)(active ? sym : BLANK);
            s_adv[tid] = advance;
        }
        __syncthreads();
        for (int i = bid * NTHR + tid; i < B * H; i += G * NTHR) {
            int b = i >> 10;
            float hf = s_adv[b] ? g_h2[dp][i] : g_h[i];
            float cf = s_adv[b] ? g_c2[dp][i] : g_c[i];
            out[B * NSTEP + i] = hf;
            out[B * NSTEP + B * H + i] = cf;
        }
    }
}

extern "C" void kernel_launch(void* const* d_in, const int* in_sizes, int n_in,
                              void* d_out, int out_size) {
    (void)in_sizes; (void)n_in; (void)out_size;
    const float* enc     = (const float*)d_in[0];
    const int*   lens    = (const int*)d_in[1];
    const float* emb     = (const float*)d_in[2];
    const float* Wx      = (const float*)d_in[3];
    const float* Wh      = (const float*)d_in[4];
    const float* bias    = (const float*)d_in[5];
    const float* W_enc   = (const float*)d_in[6];
    const float* W_pred  = (const float*)d_in[7];
    const float* b_joint = (const float*)d_in[8];
    const float* W_out   = (const float*)d_in[9];
    const float* b_out   = (const float*)d_in[10];
    float* out = (float*)d_out;

    static int configured = 0;
    if (!configured) {
        cudaFuncSetAttribute(k_decode, cudaFuncAttributeMaxDynamicSharedMemorySize,
                             SMEM_FLOATS * 4);
        configured = 1;
    }

    k_setup1<<<2816, dim3(32, 8)>>>(enc, W_pred);
    k_setup2<<<G * 64 + 128 * 1024 + 513 * 32, 448>>>(W_out, Wx, Wh);
    k_egemm<<<dim3(4, T), 256>>>(W_enc, b_joint);
    k_decode<<<G, NTHR, SMEM_FLOATS * 4>>>(emb, bias, b_out, lens, out);
}